// round 1
// baseline (speedup 1.0000x reference)
#include <cuda_runtime.h>
#include <cstdint>

// Problem constants (from reference setup_inputs)
#define BATCH     64
#define NPER      786432            // pixels per row
#define VPER      (NPER / 4)        // int4 vectors per row = 196608
#define LEVELS    256
#define HTHREADS  256
#define BLOCKS_PER_ROW 18           // 64*18 = 1152 CTAs ~ 1 wave at 8 CTAs/SM

// Global per-row histogram scratch (no cudaMalloc allowed)
__device__ unsigned int g_hist[BATCH * LEVELS];

// ---------------------------------------------------------------------------
// Kernel 0: zero the scratch
// ---------------------------------------------------------------------------
__global__ void zero_hist_kernel() {
    int i = blockIdx.x * blockDim.x + threadIdx.x;
    if (i < BATCH * LEVELS) g_hist[i] = 0u;
}

// ---------------------------------------------------------------------------
// Kernel 1: per-row histogram.
// grid = (BLOCKS_PER_ROW, BATCH), block = 256 threads (8 warps).
// Per-warp private smem histograms (8 copies) -> block reduce -> global atomic.
// ---------------------------------------------------------------------------
__global__ __launch_bounds__(HTHREADS)
void hist_kernel(const int4* __restrict__ x) {
    __shared__ unsigned int sh[8 * LEVELS];   // 8 KB: one 256-bin copy per warp

    // zero shared histograms
    #pragma unroll
    for (int i = threadIdx.x; i < 8 * LEVELS; i += HTHREADS) sh[i] = 0u;
    __syncthreads();

    // smem byte address of this warp's private histogram
    unsigned int hbase = (unsigned int)__cvta_generic_to_shared(sh)
                       + ((threadIdx.x >> 5) << 10);   // warp * 256 * 4B

    const int b = blockIdx.y;
    const int4* __restrict__ row = x + (size_t)b * VPER;

    const int stride = gridDim.x * HTHREADS;
    for (int i = blockIdx.x * HTHREADS + threadIdx.x; i < VPER; i += stride) {
        int4 v = row[i];
        // values are guaranteed in [0,256): direct bin index.
        // red.shared = no-return smem atomic add (ATOMS, dead-result-free)
        asm volatile("red.shared.add.u32 [%0], %1;"
                     :: "r"(hbase + ((unsigned)v.x << 2)), "r"(1u) : "memory");
        asm volatile("red.shared.add.u32 [%0], %1;"
                     :: "r"(hbase + ((unsigned)v.y << 2)), "r"(1u) : "memory");
        asm volatile("red.shared.add.u32 [%0], %1;"
                     :: "r"(hbase + ((unsigned)v.z << 2)), "r"(1u) : "memory");
        asm volatile("red.shared.add.u32 [%0], %1;"
                     :: "r"(hbase + ((unsigned)v.w << 2)), "r"(1u) : "memory");
    }
    __syncthreads();

    // reduce the 8 warp copies; one thread per bin (256 threads = 256 bins)
    int bin = threadIdx.x;
    unsigned int s = 0;
    #pragma unroll
    for (int c = 0; c < 8; c++) s += sh[c * LEVELS + bin];
    if (s) atomicAdd(&g_hist[b * LEVELS + bin], s);
}

// ---------------------------------------------------------------------------
// Kernel 2: broadcast hist[b][l] across 256 columns as float32.
// One float4 per thread: total B*256*256/4 = 1,048,576 float4 stores.
// ---------------------------------------------------------------------------
__global__ __launch_bounds__(256)
void bcast_kernel(float4* __restrict__ out) {
    int idx = blockIdx.x * blockDim.x + threadIdx.x;   // [0, 1048576)
    int l = (idx >> 6) & (LEVELS - 1);
    int b = idx >> 14;
    float v = (float)__ldg(&g_hist[b * LEVELS + l]);
    out[idx] = make_float4(v, v, v, v);
}

// ---------------------------------------------------------------------------
extern "C" void kernel_launch(void* const* d_in, const int* in_sizes, int n_in,
                              void* d_out, int out_size) {
    const int4* x = (const int4*)d_in[0];
    float4* out = (float4*)d_out;

    zero_hist_kernel<<<(BATCH * LEVELS + 255) / 256, 256>>>();

    dim3 hgrid(BLOCKS_PER_ROW, BATCH);
    hist_kernel<<<hgrid, HTHREADS>>>(x);

    const int total_vec4 = BATCH * LEVELS * LEVELS / 4;   // 1,048,576
    bcast_kernel<<<total_vec4 / 256, 256>>>(out);
}

// round 2
// speedup vs baseline: 1.1635x; 1.1635x over previous
#include <cuda_runtime.h>
#include <cstdint>

// Problem constants (from reference setup_inputs)
#define BATCH     64
#define NPER      786432                 // pixels per row
#define VPER      (NPER / 4)             // int4 vectors per row = 196608
#define LEVELS    256
#define HTHREADS  256
#define BPR       16                     // blocks per row -> 1024 CTAs = 1 wave @7/SM
#define V_PER_BLOCK (VPER / BPR)         // 12288 int4 per block
#define ITERS     (V_PER_BLOCK / HTHREADS) // 48 int4 per thread

// Per-(row, block) partial histograms. Written unconditionally every call
// (pure overwrite -> no zeroing kernel, deterministic under graph replay).
__device__ unsigned int g_part[BATCH * BPR * LEVELS];   // 1 MB

// ---------------------------------------------------------------------------
// Kernel 1: per-row histogram, bank-conflict-free lane-private smem counters.
// grid = (BPR, BATCH), block = 256 threads.
// Layout: sh[v*32 + lane]  -> smem bank == lane  -> zero bank conflicts on RED.
// Inter-warp races on the same (v, lane) counter are resolved by red.shared.
// ---------------------------------------------------------------------------
__global__ __launch_bounds__(HTHREADS)
void hist_kernel(const int4* __restrict__ x) {
    __shared__ unsigned int sh[LEVELS * 32];   // 32 KB

    // zero the 8192 counters (32 STS per thread)
    #pragma unroll
    for (int i = threadIdx.x; i < LEVELS * 32; i += HTHREADS) sh[i] = 0u;
    __syncthreads();

    const unsigned lane = threadIdx.x & 31u;
    // byte address of this lane's column; bin v lives at hbase + (v << 7)
    unsigned int hbase = (unsigned int)__cvta_generic_to_shared(sh) + (lane << 2);

    const int b = blockIdx.y;
    const int4* __restrict__ blk =
        x + (size_t)b * VPER + (size_t)blockIdx.x * V_PER_BLOCK;

    #pragma unroll 4
    for (int it = 0; it < ITERS; it++) {
        int4 v = blk[it * HTHREADS + threadIdx.x];
        asm volatile("red.shared.add.u32 [%0], %1;"
                     :: "r"(hbase + ((unsigned)v.x << 7)), "r"(1u) : "memory");
        asm volatile("red.shared.add.u32 [%0], %1;"
                     :: "r"(hbase + ((unsigned)v.y << 7)), "r"(1u) : "memory");
        asm volatile("red.shared.add.u32 [%0], %1;"
                     :: "r"(hbase + ((unsigned)v.z << 7)), "r"(1u) : "memory");
        asm volatile("red.shared.add.u32 [%0], %1;"
                     :: "r"(hbase + ((unsigned)v.w << 7)), "r"(1u) : "memory");
    }
    __syncthreads();

    // Reduce 32 lane-copies of bin t; rotate start by t to stay conflict-free.
    const unsigned t = threadIdx.x;
    unsigned int s = 0;
    #pragma unroll
    for (int c = 0; c < 32; c++) s += sh[t * 32 + ((c + t) & 31u)];

    // unconditional overwrite of this block's partial
    g_part[((unsigned)b * BPR + blockIdx.x) * LEVELS + t] = s;
}

// ---------------------------------------------------------------------------
// Kernel 2: sum the BPR partials per (row, bin), broadcast across 256 columns.
// grid = (4, BATCH): block q covers bins [q*64, q*64+64) of row b.
// Each block writes 64 rows x 256 cols = 4096 float4 (16 per thread, coalesced).
// ---------------------------------------------------------------------------
__global__ __launch_bounds__(256)
void bcast_kernel(float4* __restrict__ out) {
    __shared__ float sh[64];

    const int b = blockIdx.y;
    const int q = blockIdx.x;

    if (threadIdx.x < 64) {
        const int l = q * 64 + threadIdx.x;
        unsigned int s = 0;
        #pragma unroll
        for (int p = 0; p < BPR; p++)
            s += g_part[((unsigned)b * BPR + p) * LEVELS + l];
        sh[threadIdx.x] = (float)s;
    }
    __syncthreads();

    float4* __restrict__ dst =
        out + ((size_t)b * LEVELS + (size_t)q * 64) * (LEVELS / 4);

    #pragma unroll
    for (int i = threadIdx.x; i < 64 * (LEVELS / 4); i += 256) {
        float v = sh[i >> 6];
        dst[i] = make_float4(v, v, v, v);
    }
}

// ---------------------------------------------------------------------------
extern "C" void kernel_launch(void* const* d_in, const int* in_sizes, int n_in,
                              void* d_out, int out_size) {
    const int4* x = (const int4*)d_in[0];
    float4* out = (float4*)d_out;

    dim3 hgrid(BPR, BATCH);
    hist_kernel<<<hgrid, HTHREADS>>>(x);

    dim3 bgrid(4, BATCH);
    bcast_kernel<<<bgrid, 256>>>(out);
}